// round 1
// baseline (speedup 1.0000x reference)
#include <cuda_runtime.h>

// Graph_Learn: S[b,t,i,j] = exp(relu(sum_f a_f*|x[bt,i,f]-x[bt,j,f]|)) normalized
// by column-sum denom (== row sum by exact symmetry).
//
// B*T = 32 slices, V = 256 nodes, F = 64 features.
// One block = (bt, 8-row tile), 256 threads (thread = column j).
// Full x[bt] slice (256x64 f32) staged in SMEM, padded to 68 floats/row so
// per-thread LDS.128 chunk loads are conflict-free (odd 16B-quad stride).

#define Vn 256
#define Fn 64
#define Rr 8            // rows per block
#define PAD 68          // floats per smem row (17 * 16B)

#define SMEM_XS   (Vn * PAD)          // 17408 floats
#define SMEM_AS   (SMEM_XS)           // a[64]
#define SMEM_WS   (SMEM_XS + Fn)      // wsum[Rr][8]
#define SMEM_RD   (SMEM_WS + Rr * 8)  // rdn[Rr]
#define SMEM_FLOATS (SMEM_RD + Rr)
#define SMEM_BYTES  (SMEM_FLOATS * 4) // ~70.4 KB

__global__ __launch_bounds__(256, 3)
void gl_kernel(const float* __restrict__ x, const float* __restrict__ a,
               float* __restrict__ out, int grid_bt)
{
    extern __shared__ float sm[];
    float* xs   = sm;            // [Vn][PAD]
    float* as_  = sm + SMEM_AS;  // [Fn]
    float* wsum = sm + SMEM_WS;  // [Rr][8]
    float* rdn  = sm + SMEM_RD;  // [Rr]

    const int tid = threadIdx.x;
    const int bt  = blockIdx.x;
    const int i0  = blockIdx.y * Rr;

    // ---- stage x[bt] slice into padded smem (coalesced LDG.128) ----
    const float4* xp = (const float4*)(x + (size_t)bt * Vn * Fn);
    #pragma unroll
    for (int it = 0; it < (Vn * Fn / 4) / 256; ++it) {
        int k = tid + it * 256;
        float4 v = xp[k];
        int row = k >> 4;          // 16 float4 per logical row
        int fc  = (k & 15) << 2;
        *(float4*)&xs[row * PAD + fc] = v;
    }
    if (tid < Fn) as_[tid] = a[tid];
    __syncthreads();

    float acc[Rr];
    #pragma unroll
    for (int r = 0; r < Rr; ++r) acc[r] = 0.f;

    const int j = tid;

    // ---- main: 4 f-chunks of 16; xj + a chunk held in registers ----
    #pragma unroll 1
    for (int c = 0; c < 4; ++c) {
        const int f0 = c << 4;
        float xj[16], av[16];
        #pragma unroll
        for (int q = 0; q < 4; ++q) {
            float4 t  = *(const float4*)&xs[j * PAD + f0 + q * 4];
            xj[4*q+0] = t.x; xj[4*q+1] = t.y; xj[4*q+2] = t.z; xj[4*q+3] = t.w;
            float4 ta = *(const float4*)&as_[f0 + q * 4];
            av[4*q+0] = ta.x; av[4*q+1] = ta.y; av[4*q+2] = ta.z; av[4*q+3] = ta.w;
        }
        #pragma unroll
        for (int r = 0; r < Rr; ++r) {
            const float* xi = &xs[(i0 + r) * PAD + f0];
            float s = acc[r];
            #pragma unroll
            for (int q = 0; q < 4; ++q) {
                float4 t = *(const float4*)&xi[q * 4];   // uniform broadcast LDS.128
                float d0 = t.x - xj[4*q+0];
                float d1 = t.y - xj[4*q+1];
                float d2 = t.z - xj[4*q+2];
                float d3 = t.w - xj[4*q+3];
                d0 = __int_as_float(__float_as_int(d0) & 0x7fffffff);  // LOP3 (alu pipe)
                d1 = __int_as_float(__float_as_int(d1) & 0x7fffffff);
                d2 = __int_as_float(__float_as_int(d2) & 0x7fffffff);
                d3 = __int_as_float(__float_as_int(d3) & 0x7fffffff);
                s = fmaf(d0, av[4*q+0], s);
                s = fmaf(d1, av[4*q+1], s);
                s = fmaf(d2, av[4*q+2], s);
                s = fmaf(d3, av[4*q+3], s);
            }
            acc[r] = s;
        }
    }

    // ---- tmpS = exp(relu(score)) ----
    #pragma unroll
    for (int r = 0; r < Rr; ++r)
        acc[r] = __expf(fmaxf(acc[r], 0.f));

    // ---- denom: row sums (== column sums by exact symmetry) ----
    const int lane = tid & 31, w = tid >> 5;
    #pragma unroll
    for (int r = 0; r < Rr; ++r) {
        float v = acc[r];
        v += __shfl_xor_sync(0xffffffffu, v, 16);
        v += __shfl_xor_sync(0xffffffffu, v, 8);
        v += __shfl_xor_sync(0xffffffffu, v, 4);
        v += __shfl_xor_sync(0xffffffffu, v, 2);
        v += __shfl_xor_sync(0xffffffffu, v, 1);
        if (lane == 0) wsum[r * 8 + w] = v;
    }
    __syncthreads();
    if (tid < Rr) {
        float d = 0.f;
        #pragma unroll
        for (int q = 0; q < 8; ++q) d += wsum[tid * 8 + q];
        rdn[tid] = __fdividef(1.0f, d);
    }
    __syncthreads();

    // ---- normalize + coalesced store ----
    float* op = out + (((size_t)bt * Vn + i0) * Vn) + j;
    #pragma unroll
    for (int r = 0; r < Rr; ++r)
        op[(size_t)r * Vn] = acc[r] * rdn[r];
}

extern "C" void kernel_launch(void* const* d_in, const int* in_sizes, int n_in,
                              void* d_out, int out_size)
{
    const float* x = (const float*)d_in[0];
    const float* a = (const float*)d_in[1];
    // defensive: identify a (64 elems) vs x regardless of metadata order
    if (n_in >= 2 && in_sizes[0] == Fn && in_sizes[1] > Fn) {
        x = (const float*)d_in[1];
        a = (const float*)d_in[0];
    }
    int bt = in_sizes[0] == Fn ? in_sizes[1] / (Vn * Fn) : in_sizes[0] / (Vn * Fn);

    cudaFuncSetAttribute(gl_kernel, cudaFuncAttributeMaxDynamicSharedMemorySize,
                         SMEM_BYTES);
    dim3 grid(bt, Vn / Rr);
    gl_kernel<<<grid, 256, SMEM_BYTES>>>(x, a, (float*)d_out, bt);
}

// round 3
// speedup vs baseline: 1.0904x; 1.0904x over previous
#include <cuda_runtime.h>
#include <cstdint>

// Graph_Learn, Blackwell packed-f32x2 version.
// S[b,t,i,j] = exp(relu(sum_f a_f*|x[bt,i,f]-x[bt,j,f]|)) / rowsum
// (column-sum denom == row sum by exact bitwise symmetry of tmpS).

#define Vn 256
#define Fn 64
#define Rr 8            // rows per block
#define PAD 68          // floats per smem row (17 * 16B, odd quad stride)

#define SMEM_XS   (Vn * PAD)
#define SMEM_AS   (SMEM_XS)           // a[64]
#define SMEM_WS   (SMEM_XS + Fn)      // wsum[Rr][8]
#define SMEM_RD   (SMEM_WS + Rr * 8)  // rdn[Rr]
#define SMEM_FLOATS (SMEM_RD + Rr)
#define SMEM_BYTES  (SMEM_FLOATS * 4)

typedef unsigned long long u64;

__device__ __forceinline__ u64 f2add(u64 a, u64 b) {
    u64 d; asm("add.rn.f32x2 %0,%1,%2;" : "=l"(d) : "l"(a), "l"(b)); return d;
}
__device__ __forceinline__ u64 f2fma(u64 a, u64 b, u64 c) {
    u64 d; asm("fma.rn.f32x2 %0,%1,%2,%3;" : "=l"(d) : "l"(a), "l"(b), "l"(c)); return d;
}
__device__ __forceinline__ u64 f2abs(u64 a) {
    u64 d; asm("and.b64 %0,%1,0x7FFFFFFF7FFFFFFF;" : "=l"(d) : "l"(a)); return d;
}
__device__ __forceinline__ u64 packf2(float lo, float hi) {
    u64 d; asm("mov.b64 %0,{%1,%2};" : "=l"(d) : "f"(lo), "f"(hi)); return d;
}
__device__ __forceinline__ void unpackf2(u64 v, float& lo, float& hi) {
    asm("mov.b64 {%0,%1},%2;" : "=f"(lo), "=f"(hi) : "l"(v));
}
__device__ __forceinline__ void lds_2x64(uint32_t addr, u64& p0, u64& p1) {
    asm volatile("ld.shared.v2.u64 {%0,%1},[%2];" : "=l"(p0), "=l"(p1) : "r"(addr));
}

__global__ __launch_bounds__(256, 3)
void gl_kernel(const float* __restrict__ x, const float* __restrict__ a,
               float* __restrict__ out, int grid_bt)
{
    extern __shared__ float sm[];
    float* xs   = sm;            // [Vn][PAD]
    float* as_  = sm + SMEM_AS;
    float* wsum = sm + SMEM_WS;
    float* rdn  = sm + SMEM_RD;

    const int tid = threadIdx.x;
    const int bt  = blockIdx.x;
    const int i0  = blockIdx.y * Rr;

    // ---- stage x[bt] slice into padded smem (coalesced LDG.128) ----
    const float4* xp = (const float4*)(x + (size_t)bt * Vn * Fn);
    #pragma unroll
    for (int it = 0; it < (Vn * Fn / 4) / 256; ++it) {
        int k = tid + it * 256;
        float4 v = xp[k];
        int row = k >> 4;
        int fc  = (k & 15) << 2;
        *(float4*)&xs[row * PAD + fc] = v;
    }
    if (tid < Fn) as_[tid] = a[tid];
    __syncthreads();

    const uint32_t xs_sh = (uint32_t)__cvta_generic_to_shared(xs);
    const uint32_t as_sh = (uint32_t)__cvta_generic_to_shared(as_);
    const int j = tid;

    u64 acc2[Rr];
    #pragma unroll
    for (int r = 0; r < Rr; ++r) acc2[r] = 0ull;

    // ---- main: 4 f-chunks of 16 (8 packed pairs per chunk) ----
    #pragma unroll 1
    for (int c = 0; c < 4; ++c) {
        const int f0 = c << 4;
        u64 nxj[8], av[8];
        {
            const uint32_t jb = xs_sh + (uint32_t)((j * PAD + f0) * 4);
            u64 t[8];
            lds_2x64(jb +  0, t[0], t[1]);
            lds_2x64(jb + 16, t[2], t[3]);
            lds_2x64(jb + 32, t[4], t[5]);
            lds_2x64(jb + 48, t[6], t[7]);
            #pragma unroll
            for (int k = 0; k < 8; ++k) {
                float lo, hi; unpackf2(t[k], lo, hi);
                nxj[k] = packf2(-lo, -hi);
            }
            const uint32_t ab = as_sh + (uint32_t)(f0 * 4);
            lds_2x64(ab +  0, av[0], av[1]);
            lds_2x64(ab + 16, av[2], av[3]);
            lds_2x64(ab + 32, av[4], av[5]);
            lds_2x64(ab + 48, av[6], av[7]);
        }
        #pragma unroll
        for (int r = 0; r < Rr; ++r) {
            const uint32_t base = xs_sh + (uint32_t)(((i0 + r) * PAD + f0) * 4);
            u64 xi[8];
            lds_2x64(base +  0, xi[0], xi[1]);   // uniform broadcast LDS.128
            lds_2x64(base + 16, xi[2], xi[3]);
            lds_2x64(base + 32, xi[4], xi[5]);
            lds_2x64(base + 48, xi[6], xi[7]);
            u64 s = acc2[r];
            #pragma unroll
            for (int k = 0; k < 8; ++k) {
                u64 d = f2abs(f2add(xi[k], nxj[k]));   // ADD2 + 2xLOP3
                s = f2fma(d, av[k], s);                // FFMA2
            }
            acc2[r] = s;
        }
    }

    // ---- tmpS = exp(relu(lo+hi)) ----
    float acc[Rr];
    #pragma unroll
    for (int r = 0; r < Rr; ++r) {
        float lo, hi;
        unpackf2(acc2[r], lo, hi);
        acc[r] = __expf(fmaxf(lo + hi, 0.f));
    }

    // ---- denom: row sums (== column sums by symmetry) ----
    const int lane = tid & 31, w = tid >> 5;
    #pragma unroll
    for (int r = 0; r < Rr; ++r) {
        float v = acc[r];
        v += __shfl_xor_sync(0xffffffffu, v, 16);
        v += __shfl_xor_sync(0xffffffffu, v, 8);
        v += __shfl_xor_sync(0xffffffffu, v, 4);
        v += __shfl_xor_sync(0xffffffffu, v, 2);
        v += __shfl_xor_sync(0xffffffffu, v, 1);
        if (lane == 0) wsum[r * 8 + w] = v;
    }
    __syncthreads();
    if (tid < Rr) {
        float d = 0.f;
        #pragma unroll
        for (int q = 0; q < 8; ++q) d += wsum[tid * 8 + q];
        rdn[tid] = __fdividef(1.0f, d);
    }
    __syncthreads();

    // ---- normalize + coalesced store ----
    float* op = out + (((size_t)bt * Vn + i0) * Vn) + j;
    #pragma unroll
    for (int r = 0; r < Rr; ++r)
        op[(size_t)r * Vn] = acc[r] * rdn[r];
}

extern "C" void kernel_launch(void* const* d_in, const int* in_sizes, int n_in,
                              void* d_out, int out_size)
{
    const float* x = (const float*)d_in[0];
    const float* a = (const float*)d_in[1];
    if (n_in >= 2 && in_sizes[0] == Fn && in_sizes[1] > Fn) {
        x = (const float*)d_in[1];
        a = (const float*)d_in[0];
    }
    int bt = in_sizes[0] == Fn ? in_sizes[1] / (Vn * Fn) : in_sizes[0] / (Vn * Fn);

    cudaFuncSetAttribute(gl_kernel, cudaFuncAttributeMaxDynamicSharedMemorySize,
                         SMEM_BYTES);
    dim3 grid(bt, Vn / Rr);
    gl_kernel<<<grid, 256, SMEM_BYTES>>>(x, a, (float*)d_out, bt);
}